// round 6
// baseline (speedup 1.0000x reference)
#include <cuda_runtime.h>
#include <cuda_fp16.h>
#include <cstdint>
#include <cmath>

#define BATCH 32768
#define HDIM  512
#define NL    5

// ---------------- static device buffers ----------------
#define S2E_SZ (512*512)
#define TF_SZ  (512*1024)
#define S2E_OFF 0
#define TF_OFF  (S2E_OFF + 5*S2E_SZ)
#define FG_OFF  (TF_OFF  + 5*TF_SZ)
#define FW_OFF  (FG_OFF  + 5*S2E_SZ)
#define WG_OFF  (FW_OFF  + 5*TF_SZ)
#define H1_OFF  (WG_OFF  + 5*S2E_SZ)
#define WP_TOTAL (H1_OFF + 4*S2E_SZ)

__device__ __half g_WP[WP_TOTAL];
// per row: [sh_h(512) e_h f_h w_h | sh_l e_l f_l w_l] -> 4096 halves
__device__ __half g_MEGA[(size_t)BATCH * 4096];
__device__ __half g_SCRATCH[(size_t)BATCH * 512];   // fm/wm hi only
__device__ __half g_HEADH[(size_t)4 * BATCH * 512]; // head hiddens hi only

struct Bias4 { const float* p[4]; };

// ---------------- helpers ----------------
__device__ __forceinline__ void cp16s(uint32_t sa, const void* g) {
    asm volatile("cp.async.cg.shared.global [%0], [%1], 16;" :: "r"(sa), "l"(g));
}
__device__ __forceinline__ void ldmx4(uint32_t addr, uint32_t& r0, uint32_t& r1, uint32_t& r2, uint32_t& r3) {
    asm volatile("ldmatrix.sync.aligned.m8n8.x4.shared.b16 {%0,%1,%2,%3}, [%4];"
        : "=r"(r0), "=r"(r1), "=r"(r2), "=r"(r3) : "r"(addr));
}
#define MMA16(acc, a0,a1,a2,a3, b0,b1) \
    asm volatile("mma.sync.aligned.m16n8k16.row.col.f32.f16.f16.f32 " \
        "{%0,%1,%2,%3},{%4,%5,%6,%7},{%8,%9},{%0,%1,%2,%3};" \
        : "+f"((acc)[0]), "+f"((acc)[1]), "+f"((acc)[2]), "+f"((acc)[3]) \
        : "r"(a0), "r"(a1), "r"(a2), "r"(a3), "r"(b0), "r"(b1))

// ---------------- setup kernels ----------------
__global__ void split_inputs_kernel(const float* __restrict__ sh, const float* __restrict__ e,
                                    const float* __restrict__ f,  const float* __restrict__ w) {
    int idx = blockIdx.x * 256 + threadIdx.x;
    if (idx >= BATCH * HDIM) return;
    int row = idx >> 9, k = idx & 511;
    __half* m = g_MEGA + (size_t)row * 4096;
    float v; __half h;
    v = sh[idx]; h = __float2half(v); m[k]        = h; m[2048 + k] = __float2half(v - __half2float(h));
    v = e[idx];  h = __float2half(v); m[512 + k]  = h; m[2560 + k] = __float2half(v - __half2float(h));
    v = f[idx];  h = __float2half(v); m[1024 + k] = h; m[3072 + k] = __float2half(v - __half2float(h));
    v = w[idx];  h = __float2half(v); m[1536 + k] = h; m[3584 + k] = __float2half(v - __half2float(h));
}

// tiled transpose pack: fp32 W[L][K][512] -> fp16 out[L][512][K]
__global__ void pack_tiled(const float* __restrict__ W, __half* __restrict__ out, int K) {
    __shared__ float t[32][33];
    int k0 = blockIdx.x * 32, n0 = blockIdx.y * 32, l = blockIdx.z;
    const float* Wl = W + (size_t)l * K * 512;
    __half* ol = out + (size_t)l * 512 * K;
    int r = threadIdx.x >> 5, c = threadIdx.x & 31;
    #pragma unroll
    for (int i = 0; i < 4; i++)
        t[r + 8 * i][c] = Wl[(size_t)(k0 + r + 8 * i) * 512 + n0 + c];
    __syncthreads();
    #pragma unroll
    for (int i = 0; i < 4; i++) {
        int n = n0 + r + 8 * i;
        ol[(size_t)n * K + k0 + c] = __float2half(t[c][r + 8 * i]);
    }
}

// ---------------- GEMM ----------------
#define MODE_PLAIN 0
#define MODE_ADD   1
#define MODE_GATE  2
#define MODE_GELU  3

// smem: 3 cp.async stages of (A 16K + B 16K); epilogue reuses [0, 67.6K) as fp32 tile
#define SAH(s) ((s) * 32768)
#define SBB(s) ((s) * 32768 + 16384)
#define GEMM_SMEM 98304
#define EPI_LD 132

template<int MODE>
__global__ void __launch_bounds__(256, 2) gemm_lm(
    const __half* __restrict__ A, int lda, int a_hi, int a_zs, int K,
    const __half* __restrict__ Wp, int wp_zs,
    Bias4 b4,
    __half* __restrict__ out, int ldo, int o_hi, int o_lo, int out_zs,
    const __half* __restrict__ aux, int ldx, int x_hi)
{
    extern __shared__ __align__(1024) char dsm[];
    const uint32_t sb = (uint32_t)__cvta_generic_to_shared(dsm);
    const int tid = threadIdx.x, lane = tid & 31, warp = tid >> 5;
    const int wm = warp >> 1, wn = warp & 1;
    const int bm = blockIdx.x, bn = blockIdx.y;
    const int z  = blockIdx.z;
    const int KT = K >> 6;

    a_hi += z * a_zs;
    Wp   += (size_t)z * wp_zs;
    out  += (size_t)z * out_zs;
    const float* bias = b4.p[z];

    float acc[2][8][4];
    #pragma unroll
    for (int i = 0; i < 2; i++)
        #pragma unroll
        for (int j = 0; j < 8; j++)
            #pragma unroll
            for (int q = 0; q < 4; q++) acc[i][j][q] = 0.f;

    const __half* Ab = A  + (size_t)bm * 128 * lda;
    const __half* Bb = Wp + (size_t)bn * 128 * K;

    auto load_stage = [&](int s, int kt) {
        const int k0 = kt << 6;
        #pragma unroll
        for (int i = 0; i < 4; i++) {
            const int id = tid + 256 * i;
            const int row = id >> 3, c = id & 7;
            const uint32_t sw = (row << 7) | ((c ^ (row & 7)) << 4);
            cp16s(sb + SAH(s) + sw, Ab + (size_t)row * lda + a_hi + k0 + c * 8);
            cp16s(sb + SBB(s) + sw, Bb + (size_t)row * K   + k0   + c * 8);
        }
        asm volatile("cp.async.commit_group;");
    };

    load_stage(0, 0);
    load_stage(1, 1);

    const int lrow = lane & 15;
    const int lhi  = lane >> 4;
    const int lph  = lane & 7;
    const uint32_t aRow0 = (uint32_t)(wm * 32 + lrow) << 7;
    const uint32_t bRow0 = (uint32_t)(wn * 64 + lrow) << 7;

    int s = 0;
    for (int kt = 0; kt < KT; kt++) {
        if (kt + 2 < KT) {
            int s2 = s + 2; if (s2 >= 3) s2 -= 3;
            load_stage(s2, kt + 2);
            asm volatile("cp.async.wait_group 2;");
        } else if (kt + 1 < KT) {
            asm volatile("cp.async.wait_group 1;");
        } else {
            asm volatile("cp.async.wait_group 0;");
        }
        __syncthreads();
        const uint32_t aH = sb + SAH(s);
        const uint32_t bS = sb + SBB(s);

        #pragma unroll
        for (int kq = 0; kq < 4; kq++) {
            const uint32_t cb = (uint32_t)(((kq * 2 + lhi) ^ lph) << 4);
            uint32_t ah[2][4], b[4][4];
            #pragma unroll
            for (int mi = 0; mi < 2; mi++)
                ldmx4(aH + aRow0 + (uint32_t)(mi * 2048) + cb, ah[mi][0], ah[mi][1], ah[mi][2], ah[mi][3]);
            #pragma unroll
            for (int n2 = 0; n2 < 4; n2++)
                ldmx4(bS + bRow0 + (uint32_t)(n2 * 2048) + cb, b[n2][0], b[n2][1], b[n2][2], b[n2][3]);
            #pragma unroll
            for (int mi = 0; mi < 2; mi++)
                #pragma unroll
                for (int ni = 0; ni < 8; ni++)
                    MMA16(acc[mi][ni], ah[mi][0], ah[mi][1], ah[mi][2], ah[mi][3],
                          b[ni >> 1][ni & 1], b[ni >> 1][2 + (ni & 1)]);
        }
        __syncthreads();
        if (++s >= 3) s -= 3;
    }

    // ---- epilogue: stage accumulators in smem, then coalesced vector I/O ----
    float* S = (float*)dsm;
    #pragma unroll
    for (int mi = 0; mi < 2; mi++) {
        #pragma unroll
        for (int ni = 0; ni < 8; ni++) {
            const int r0 = wm * 32 + mi * 16 + (lane >> 2);
            const int c  = wn * 64 + ni * 8 + (lane & 3) * 2;
            S[r0 * EPI_LD + c]           = acc[mi][ni][0];
            S[r0 * EPI_LD + c + 1]       = acc[mi][ni][1];
            S[(r0 + 8) * EPI_LD + c]     = acc[mi][ni][2];
            S[(r0 + 8) * EPI_LD + c + 1] = acc[mi][ni][3];
        }
    }
    __syncthreads();

    const int row = tid >> 1;
    const int ch  = (tid & 1) * 64;
    const int gr  = bm * 128 + row;
    __half* orow = out + (size_t)gr * ldo;
    const __half* xrow = (MODE == MODE_GATE) ? (aux + (size_t)gr * ldx) : nullptr;

    #pragma unroll
    for (int j = 0; j < 64; j += 8) {
        const int c  = ch + j;
        const int gc = bn * 128 + c;
        float4 s0 = *(float4*)&S[row * EPI_LD + c];
        float4 s1 = *(float4*)&S[row * EPI_LD + c + 4];
        float4 b0 = *(const float4*)(bias + gc);
        float4 b1 = *(const float4*)(bias + gc + 4);
        float v[8] = { s0.x + b0.x, s0.y + b0.y, s0.z + b0.z, s0.w + b0.w,
                       s1.x + b1.x, s1.y + b1.y, s1.z + b1.z, s1.w + b1.w };

        if (MODE == MODE_ADD || MODE == MODE_GATE) {
            uint4 ohv = *(const uint4*)(orow + o_hi + gc);
            uint4 olv = *(const uint4*)(orow + o_lo + gc);
            const __half2* oh = (const __half2*)&ohv;
            const __half2* ol = (const __half2*)&olv;
            float old[8];
            #pragma unroll
            for (int q = 0; q < 4; q++) {
                float2 a = __half22float2(oh[q]);
                float2 b = __half22float2(ol[q]);
                old[2 * q]     = a.x + b.x;
                old[2 * q + 1] = a.y + b.y;
            }
            if (MODE == MODE_ADD) {
                #pragma unroll
                for (int i = 0; i < 8; i++) v[i] += old[i];
            } else {
                uint4 xv = *(const uint4*)(xrow + x_hi + gc);
                const __half2* xh = (const __half2*)&xv;
                #pragma unroll
                for (int q = 0; q < 4; q++) {
                    float2 m = __half22float2(xh[q]);
                    float g0 = 1.f / (1.f + expf(-v[2 * q]));
                    float g1 = 1.f / (1.f + expf(-v[2 * q + 1]));
                    v[2 * q]     = old[2 * q]     + (m.x - old[2 * q])     * g0;
                    v[2 * q + 1] = old[2 * q + 1] + (m.y - old[2 * q + 1]) * g1;
                }
            }
        }
        if (MODE == MODE_GELU) {
            #pragma unroll
            for (int i = 0; i < 8; i++)
                v[i] = 0.5f * v[i] * (1.f + erff(v[i] * 0.70710678118654752f));
        }

        uint4 hv, lv;
        __half* hh = (__half*)&hv;
        __half* hl = (__half*)&lv;
        #pragma unroll
        for (int i = 0; i < 8; i++) {
            hh[i] = __float2half(v[i]);
            hl[i] = __float2half(v[i] - __half2float(hh[i]));
        }
        *(uint4*)(orow + o_hi + gc) = hv;
        if (MODE == MODE_ADD || MODE == MODE_GATE)
            *(uint4*)(orow + o_lo + gc) = lv;
    }
}

// ---------------- final tiny projections ----------------
__global__ void head2_kernel(
    const float* __restrict__ hsW2, const float* __restrict__ hsb2,
    const float* __restrict__ heW2, const float* __restrict__ heb2,
    const float* __restrict__ hfW2, const float* __restrict__ hfb2,
    const float* __restrict__ hwW2, const float* __restrict__ hwb2,
    float* __restrict__ out)
{
    int row  = blockIdx.x * 8 + (threadIdx.x >> 5);
    int lane = threadIdx.x & 31;
    const __half* h0 = g_HEADH + (size_t)row * 512;
    const __half* h1 = g_HEADH + (size_t)(BATCH + row) * 512;
    const __half* h2 = g_HEADH + (size_t)(2 * BATCH + row) * 512;
    const __half* h3 = g_HEADH + (size_t)(3 * BATCH + row) * 512;
    float acc[7] = {0.f, 0.f, 0.f, 0.f, 0.f, 0.f, 0.f};
    for (int k = lane; k < 512; k += 32) {
        float x0 = __half2float(h0[k]);
        float x1 = __half2float(h1[k]);
        float x2 = __half2float(h2[k]);
        float x3 = __half2float(h3[k]);
        acc[0] = fmaf(x0, hsW2[k * 3 + 0], acc[0]);
        acc[1] = fmaf(x0, hsW2[k * 3 + 1], acc[1]);
        acc[2] = fmaf(x0, hsW2[k * 3 + 2], acc[2]);
        acc[3] = fmaf(x1, heW2[k],         acc[3]);
        acc[4] = fmaf(x2, hfW2[k],         acc[4]);
        acc[5] = fmaf(x3, hwW2[k * 2 + 0], acc[5]);
        acc[6] = fmaf(x3, hwW2[k * 2 + 1], acc[6]);
    }
    #pragma unroll
    for (int j = 0; j < 7; j++)
        #pragma unroll
        for (int o = 16; o > 0; o >>= 1)
            acc[j] += __shfl_xor_sync(0xffffffffu, acc[j], o);
    if (lane == 0) {
        float* orow = out + (size_t)row * 7;
        orow[0] = acc[0] + hsb2[0];
        orow[1] = acc[1] + hsb2[1];
        orow[2] = acc[2] + hsb2[2];
        orow[3] = acc[3] + heb2[0];
        orow[4] = acc[4] + hfb2[0];
        orow[5] = acc[5] + hwb2[0];
        orow[6] = acc[6] + hwb2[1];
    }
}

// ---------------- host launch ----------------
extern "C" void kernel_launch(void* const* d_in, const int* in_sizes, int n_in,
                              void* d_out, int out_size) {
    (void)in_sizes; (void)n_in; (void)out_size;
    const float* sh    = (const float*)d_in[0];
    const float* el    = (const float*)d_in[1];
    const float* fa    = (const float*)d_in[2];
    const float* wr    = (const float*)d_in[3];
    const float* s2e_W = (const float*)d_in[4];
    const float* s2e_b = (const float*)d_in[5];
    const float* tf_W  = (const float*)d_in[6];
    const float* tf_b  = (const float*)d_in[7];
    const float* fw_W  = (const float*)d_in[8];
    const float* fw_b  = (const float*)d_in[9];
    const float* fg_W  = (const float*)d_in[10];
    const float* fg_b  = (const float*)d_in[11];
    const float* wg_W  = (const float*)d_in[12];
    const float* wg_b  = (const float*)d_in[13];
    const float* hsW1  = (const float*)d_in[14];
    const float* hsb1  = (const float*)d_in[15];
    const float* hsW2  = (const float*)d_in[16];
    const float* hsb2  = (const float*)d_in[17];
    const float* heW1  = (const float*)d_in[18];
    const float* heb1  = (const float*)d_in[19];
    const float* heW2  = (const float*)d_in[20];
    const float* heb2  = (const float*)d_in[21];
    const float* hfW1  = (const float*)d_in[22];
    const float* hfb1  = (const float*)d_in[23];
    const float* hfW2  = (const float*)d_in[24];
    const float* hfb2  = (const float*)d_in[25];
    const float* hwW1  = (const float*)d_in[26];
    const float* hwb1  = (const float*)d_in[27];
    const float* hwW2  = (const float*)d_in[28];
    const float* hwb2  = (const float*)d_in[29];

    __half *WP, *MEGA, *SCRATCH, *HEADH;
    cudaGetSymbolAddress((void**)&WP,      g_WP);
    cudaGetSymbolAddress((void**)&MEGA,    g_MEGA);
    cudaGetSymbolAddress((void**)&SCRATCH, g_SCRATCH);
    cudaGetSymbolAddress((void**)&HEADH,   g_HEADH);

    cudaFuncSetAttribute(gemm_lm<MODE_PLAIN>, cudaFuncAttributeMaxDynamicSharedMemorySize, GEMM_SMEM);
    cudaFuncSetAttribute(gemm_lm<MODE_ADD>,   cudaFuncAttributeMaxDynamicSharedMemorySize, GEMM_SMEM);
    cudaFuncSetAttribute(gemm_lm<MODE_GATE>,  cudaFuncAttributeMaxDynamicSharedMemorySize, GEMM_SMEM);
    cudaFuncSetAttribute(gemm_lm<MODE_GELU>,  cudaFuncAttributeMaxDynamicSharedMemorySize, GEMM_SMEM);

    split_inputs_kernel<<<(BATCH * HDIM + 255) / 256, 256>>>(sh, el, fa, wr);

    pack_tiled<<<dim3(16, 16, 5), 256>>>(s2e_W, WP + S2E_OFF, 512);
    pack_tiled<<<dim3(32, 16, 5), 256>>>(tf_W,  WP + TF_OFF,  1024);
    pack_tiled<<<dim3(16, 16, 5), 256>>>(fg_W,  WP + FG_OFF,  512);
    pack_tiled<<<dim3(32, 16, 5), 256>>>(fw_W,  WP + FW_OFF,  1024);
    pack_tiled<<<dim3(16, 16, 5), 256>>>(wg_W,  WP + WG_OFF,  512);
    pack_tiled<<<dim3(16, 16, 1), 256>>>(hsW1, WP + H1_OFF + 0 * S2E_SZ, 512);
    pack_tiled<<<dim3(16, 16, 1), 256>>>(heW1, WP + H1_OFF + 1 * S2E_SZ, 512);
    pack_tiled<<<dim3(16, 16, 1), 256>>>(hfW1, WP + H1_OFF + 2 * S2E_SZ, 512);
    pack_tiled<<<dim3(16, 16, 1), 256>>>(hwW1, WP + H1_OFF + 3 * S2E_SZ, 512);

    dim3 grid(BATCH / 128, 4, 1);
    auto B1 = [](const float* p) { Bias4 b; b.p[0] = b.p[1] = b.p[2] = b.p[3] = p; return b; };

    for (int i = 0; i < NL; i++) {
        // e = e + sh @ W + b
        gemm_lm<MODE_ADD><<<grid, 256, GEMM_SMEM>>>(
            MEGA, 4096, 0, 0, 512,
            WP + S2E_OFF + (size_t)i * S2E_SZ, 0, B1(s2e_b + i * 512),
            MEGA, 4096, 512, 2560, 0, nullptr, 0, 0);
        // fm = [sh_hi, e_hi] @ W + b -> SCRATCH (hi only)
        gemm_lm<MODE_PLAIN><<<grid, 256, GEMM_SMEM>>>(
            MEGA, 4096, 0, 0, 1024,
            WP + TF_OFF + (size_t)i * TF_SZ, 0, B1(tf_b + i * 512),
            SCRATCH, 512, 0, 0, 0, nullptr, 0, 0);
        // g = sigmoid(fm @ W + b); f = f*(1-g) + fm*g
        gemm_lm<MODE_GATE><<<grid, 256, GEMM_SMEM>>>(
            SCRATCH, 512, 0, 0, 512,
            WP + FG_OFF + (size_t)i * S2E_SZ, 0, B1(fg_b + i * 512),
            MEGA, 4096, 1024, 3072, 0, SCRATCH, 512, 0);
        // wm = [e_hi, f_hi] @ W + b
        gemm_lm<MODE_PLAIN><<<grid, 256, GEMM_SMEM>>>(
            MEGA, 4096, 512, 0, 1024,
            WP + FW_OFF + (size_t)i * TF_SZ, 0, B1(fw_b + i * 512),
            SCRATCH, 512, 0, 0, 0, nullptr, 0, 0);
        // g = sigmoid(wm @ W + b); w = w*(1-g) + wm*g
        gemm_lm<MODE_GATE><<<grid, 256, GEMM_SMEM>>>(
            SCRATCH, 512, 0, 0, 512,
            WP + WG_OFF + (size_t)i * S2E_SZ, 0, B1(wg_b + i * 512),
            MEGA, 4096, 1536, 3584, 0, SCRATCH, 512, 0);
    }

    // all 4 heads in one launch: z selects head
    {
        Bias4 hb; hb.p[0] = hsb1; hb.p[1] = heb1; hb.p[2] = hfb1; hb.p[3] = hwb1;
        dim3 grid4(BATCH / 128, 4, 4);
        gemm_lm<MODE_GELU><<<grid4, 256, GEMM_SMEM>>>(
            MEGA, 4096, 0, 512, 512,
            WP + H1_OFF, S2E_SZ, hb,
            HEADH, 512, 0, 0, BATCH * 512, nullptr, 0, 0);
    }

    head2_kernel<<<BATCH / 8, 256>>>(hsW2, hsb2, heW2, heb2, hfW2, hfb2,
                                     hwW2, hwb2, (float*)d_out);
}

// round 7
// speedup vs baseline: 1.7575x; 1.7575x over previous
#include <cuda_runtime.h>
#include <cuda_fp16.h>
#include <cstdint>
#include <cmath>

#define BATCH 32768
#define HDIM  512
#define NL    5

// ---------------- static device buffers ----------------
#define S2E_SZ (512*512)
#define TF_SZ  (512*1024)
#define S2E_OFF 0
#define TF_OFF  (S2E_OFF + 5*S2E_SZ)
#define FG_OFF  (TF_OFF  + 5*TF_SZ)
#define FW_OFF  (FG_OFF  + 5*S2E_SZ)
#define WG_OFF  (FW_OFF  + 5*TF_SZ)
#define H1_OFF  (WG_OFF  + 5*S2E_SZ)
#define WP_TOTAL (H1_OFF + 4*S2E_SZ)

__device__ __half g_WP[WP_TOTAL];
// per row: [sh_h(512) e_h f_h w_h | sh_l e_l f_l w_l] -> 4096 halves
__device__ __half g_MEGA[(size_t)BATCH * 4096];
__device__ __half g_SCRATCH[(size_t)BATCH * 512];   // fm/wm hi only
__device__ __half g_HEADH[(size_t)4 * BATCH * 512]; // head hiddens hi only

struct Bias4 { const float* p[4]; };

// ---------------- helpers ----------------
__device__ __forceinline__ void cp16s(uint32_t sa, const void* g) {
    asm volatile("cp.async.cg.shared.global [%0], [%1], 16;" :: "r"(sa), "l"(g));
}
__device__ __forceinline__ void ldmx4(uint32_t addr, uint32_t& r0, uint32_t& r1, uint32_t& r2, uint32_t& r3) {
    asm volatile("ldmatrix.sync.aligned.m8n8.x4.shared.b16 {%0,%1,%2,%3}, [%4];"
        : "=r"(r0), "=r"(r1), "=r"(r2), "=r"(r3) : "r"(addr));
}
#define MMA16(acc, a0,a1,a2,a3, b0,b1) \
    asm volatile("mma.sync.aligned.m16n8k16.row.col.f32.f16.f16.f32 " \
        "{%0,%1,%2,%3},{%4,%5,%6,%7},{%8,%9},{%0,%1,%2,%3};" \
        : "+f"((acc)[0]), "+f"((acc)[1]), "+f"((acc)[2]), "+f"((acc)[3]) \
        : "r"(a0), "r"(a1), "r"(a2), "r"(a3), "r"(b0), "r"(b1))

// ---------------- setup kernels ----------------
__global__ void split_inputs_kernel(const float* __restrict__ sh, const float* __restrict__ e,
                                    const float* __restrict__ f,  const float* __restrict__ w) {
    int idx = blockIdx.x * 256 + threadIdx.x;
    if (idx >= BATCH * HDIM) return;
    int row = idx >> 9, k = idx & 511;
    __half* m = g_MEGA + (size_t)row * 4096;
    float v; __half h;
    v = sh[idx]; h = __float2half(v); m[k]        = h; m[2048 + k] = __float2half(v - __half2float(h));
    v = e[idx];  h = __float2half(v); m[512 + k]  = h; m[2560 + k] = __float2half(v - __half2float(h));
    v = f[idx];  h = __float2half(v); m[1024 + k] = h; m[3072 + k] = __float2half(v - __half2float(h));
    v = w[idx];  h = __float2half(v); m[1536 + k] = h; m[3584 + k] = __float2half(v - __half2float(h));
}

// tiled transpose pack: fp32 W[L][K][512] -> fp16 out[L][512][K]
__global__ void pack_tiled(const float* __restrict__ W, __half* __restrict__ out, int K) {
    __shared__ float t[32][33];
    int k0 = blockIdx.x * 32, n0 = blockIdx.y * 32, l = blockIdx.z;
    const float* Wl = W + (size_t)l * K * 512;
    __half* ol = out + (size_t)l * 512 * K;
    int r = threadIdx.x >> 5, c = threadIdx.x & 31;
    #pragma unroll
    for (int i = 0; i < 4; i++)
        t[r + 8 * i][c] = Wl[(size_t)(k0 + r + 8 * i) * 512 + n0 + c];
    __syncthreads();
    #pragma unroll
    for (int i = 0; i < 4; i++) {
        int n = n0 + r + 8 * i;
        ol[(size_t)n * K + k0 + c] = __float2half(t[c][r + 8 * i]);
    }
}

// ---------------- GEMM ----------------
#define MODE_PLAIN 0
#define MODE_ADD   1
#define MODE_GATE  2
#define MODE_GELU  3

template<int MODE>
__device__ __forceinline__ void epi_store(int r, int c, float v0, float v1,
    const float* __restrict__ bias,
    __half* __restrict__ out, int ldo, int o_hi, int o_lo,
    const __half* __restrict__ aux, int ldx, int x_hi)
{
    v0 += bias[c];
    v1 += bias[c + 1];
    __half* orow = out + (size_t)r * ldo;
    if (MODE == MODE_ADD || MODE == MODE_GATE) {
        __half2 oh = *(const __half2*)(orow + o_hi + c);
        __half2 ol = *(const __half2*)(orow + o_lo + c);
        float old0 = __half2float(oh.x) + __half2float(ol.x);
        float old1 = __half2float(oh.y) + __half2float(ol.y);
        if (MODE == MODE_ADD) {
            v0 += old0; v1 += old1;
        } else {
            const __half* xrow = aux + (size_t)r * ldx;
            __half2 xh = *(const __half2*)(xrow + x_hi + c);
            float m0 = __half2float(xh.x);
            float m1 = __half2float(xh.y);
            float g0 = 1.f / (1.f + expf(-v0));
            float g1 = 1.f / (1.f + expf(-v1));
            v0 = old0 + (m0 - old0) * g0;
            v1 = old1 + (m1 - old1) * g1;
        }
    }
    if (MODE == MODE_GELU) {
        v0 = 0.5f * v0 * (1.f + erff(v0 * 0.70710678118654752f));
        v1 = 0.5f * v1 * (1.f + erff(v1 * 0.70710678118654752f));
    }
    __half h0 = __float2half(v0), h1 = __float2half(v1);
    __half2 hh; hh.x = h0; hh.y = h1;
    *(__half2*)(orow + o_hi + c) = hh;
    if (MODE == MODE_ADD || MODE == MODE_GATE) {
        __half2 ll;
        ll.x = __float2half(v0 - __half2float(h0));
        ll.y = __float2half(v1 - __half2float(h1));
        *(__half2*)(orow + o_lo + c) = ll;
    }
}

// smem per stage: A 16K + B 16K = 32K; three stages = 96K
#define SAH(s) ((s) * 32768)
#define SBB(s) ((s) * 32768 + 16384)
#define GEMM_SMEM 98304

template<int MODE>
__global__ void __launch_bounds__(256, 2) gemm_lm(
    const __half* __restrict__ A, int lda, int a_hi, int a_zs, int K,
    const __half* __restrict__ Wp, int wp_zs,
    Bias4 b4,
    __half* __restrict__ out, int ldo, int o_hi, int o_lo, int out_zs,
    const __half* __restrict__ aux, int ldx, int x_hi)
{
    extern __shared__ __align__(1024) char dsm[];
    const uint32_t sb = (uint32_t)__cvta_generic_to_shared(dsm);
    const int tid = threadIdx.x, lane = tid & 31, warp = tid >> 5;
    const int wm = warp >> 1, wn = warp & 1;
    const int bm = blockIdx.x, bn = blockIdx.y;
    const int z  = blockIdx.z;
    const int KT = K >> 6;

    a_hi += z * a_zs;
    Wp   += (size_t)z * wp_zs;
    out  += (size_t)z * out_zs;
    const float* bias = b4.p[z];

    float acc[2][8][4];
    #pragma unroll
    for (int i = 0; i < 2; i++)
        #pragma unroll
        for (int j = 0; j < 8; j++)
            #pragma unroll
            for (int q = 0; q < 4; q++) acc[i][j][q] = 0.f;

    const __half* Ab = A  + (size_t)bm * 128 * lda;
    const __half* Bb = Wp + (size_t)bn * 128 * K;

    auto load_stage = [&](int s, int kt) {
        const int k0 = kt << 6;
        #pragma unroll
        for (int i = 0; i < 4; i++) {
            const int id = tid + 256 * i;
            const int row = id >> 3, c = id & 7;
            const uint32_t sw = (row << 7) | ((c ^ (row & 7)) << 4);
            cp16s(sb + SAH(s) + sw, Ab + (size_t)row * lda + a_hi + k0 + c * 8);
            cp16s(sb + SBB(s) + sw, Bb + (size_t)row * K   + k0   + c * 8);
        }
        asm volatile("cp.async.commit_group;");
    };

    load_stage(0, 0);
    load_stage(1, 1);

    const int lrow = lane & 15;
    const int lhi  = lane >> 4;
    const int lph  = lane & 7;
    const uint32_t aRow0 = (uint32_t)(wm * 32 + lrow) << 7;
    const uint32_t bRow0 = (uint32_t)(wn * 64 + lrow) << 7;

    int s = 0;
    for (int kt = 0; kt < KT; kt++) {
        if (kt + 2 < KT) {
            int s2 = s + 2; if (s2 >= 3) s2 -= 3;
            load_stage(s2, kt + 2);
            asm volatile("cp.async.wait_group 2;");
        } else if (kt + 1 < KT) {
            asm volatile("cp.async.wait_group 1;");
        } else {
            asm volatile("cp.async.wait_group 0;");
        }
        __syncthreads();
        const uint32_t aH = sb + SAH(s);
        const uint32_t bS = sb + SBB(s);

        #pragma unroll
        for (int kq = 0; kq < 4; kq++) {
            const uint32_t cb = (uint32_t)(((kq * 2 + lhi) ^ lph) << 4);
            uint32_t ah[2][4], b[4][4];
            #pragma unroll
            for (int mi = 0; mi < 2; mi++)
                ldmx4(aH + aRow0 + (uint32_t)(mi * 2048) + cb, ah[mi][0], ah[mi][1], ah[mi][2], ah[mi][3]);
            #pragma unroll
            for (int n2 = 0; n2 < 4; n2++)
                ldmx4(bS + bRow0 + (uint32_t)(n2 * 2048) + cb, b[n2][0], b[n2][1], b[n2][2], b[n2][3]);
            #pragma unroll
            for (int mi = 0; mi < 2; mi++)
                #pragma unroll
                for (int ni = 0; ni < 8; ni++)
                    MMA16(acc[mi][ni], ah[mi][0], ah[mi][1], ah[mi][2], ah[mi][3],
                          b[ni >> 1][ni & 1], b[ni >> 1][2 + (ni & 1)]);
        }
        __syncthreads();
        if (++s >= 3) s -= 3;
    }

    #pragma unroll
    for (int mi = 0; mi < 2; mi++) {
        #pragma unroll
        for (int ni = 0; ni < 8; ni++) {
            const int r0 = bm * 128 + wm * 32 + mi * 16 + (lane >> 2);
            const int c  = bn * 128 + wn * 64 + ni * 8 + (lane & 3) * 2;
            epi_store<MODE>(r0,     c, acc[mi][ni][0], acc[mi][ni][1], bias, out, ldo, o_hi, o_lo, aux, ldx, x_hi);
            epi_store<MODE>(r0 + 8, c, acc[mi][ni][2], acc[mi][ni][3], bias, out, ldo, o_hi, o_lo, aux, ldx, x_hi);
        }
    }
}

// ---------------- final tiny projections ----------------
__global__ void head2_kernel(
    const float* __restrict__ hsW2, const float* __restrict__ hsb2,
    const float* __restrict__ heW2, const float* __restrict__ heb2,
    const float* __restrict__ hfW2, const float* __restrict__ hfb2,
    const float* __restrict__ hwW2, const float* __restrict__ hwb2,
    float* __restrict__ out)
{
    int row  = blockIdx.x * 8 + (threadIdx.x >> 5);
    int lane = threadIdx.x & 31;
    const __half* h0 = g_HEADH + (size_t)row * 512;
    const __half* h1 = g_HEADH + (size_t)(BATCH + row) * 512;
    const __half* h2 = g_HEADH + (size_t)(2 * BATCH + row) * 512;
    const __half* h3 = g_HEADH + (size_t)(3 * BATCH + row) * 512;
    float acc[7] = {0.f, 0.f, 0.f, 0.f, 0.f, 0.f, 0.f};
    for (int k = lane; k < 512; k += 32) {
        float x0 = __half2float(h0[k]);
        float x1 = __half2float(h1[k]);
        float x2 = __half2float(h2[k]);
        float x3 = __half2float(h3[k]);
        acc[0] = fmaf(x0, hsW2[k * 3 + 0], acc[0]);
        acc[1] = fmaf(x0, hsW2[k * 3 + 1], acc[1]);
        acc[2] = fmaf(x0, hsW2[k * 3 + 2], acc[2]);
        acc[3] = fmaf(x1, heW2[k],         acc[3]);
        acc[4] = fmaf(x2, hfW2[k],         acc[4]);
        acc[5] = fmaf(x3, hwW2[k * 2 + 0], acc[5]);
        acc[6] = fmaf(x3, hwW2[k * 2 + 1], acc[6]);
    }
    #pragma unroll
    for (int j = 0; j < 7; j++)
        #pragma unroll
        for (int o = 16; o > 0; o >>= 1)
            acc[j] += __shfl_xor_sync(0xffffffffu, acc[j], o);
    if (lane == 0) {
        float* orow = out + (size_t)row * 7;
        orow[0] = acc[0] + hsb2[0];
        orow[1] = acc[1] + hsb2[1];
        orow[2] = acc[2] + hsb2[2];
        orow[3] = acc[3] + heb2[0];
        orow[4] = acc[4] + hfb2[0];
        orow[5] = acc[5] + hwb2[0];
        orow[6] = acc[6] + hwb2[1];
    }
}

// ---------------- host launch ----------------
extern "C" void kernel_launch(void* const* d_in, const int* in_sizes, int n_in,
                              void* d_out, int out_size) {
    (void)in_sizes; (void)n_in; (void)out_size;
    const float* sh    = (const float*)d_in[0];
    const float* el    = (const float*)d_in[1];
    const float* fa    = (const float*)d_in[2];
    const float* wr    = (const float*)d_in[3];
    const float* s2e_W = (const float*)d_in[4];
    const float* s2e_b = (const float*)d_in[5];
    const float* tf_W  = (const float*)d_in[6];
    const float* tf_b  = (const float*)d_in[7];
    const float* fw_W  = (const float*)d_in[8];
    const float* fw_b  = (const float*)d_in[9];
    const float* fg_W  = (const float*)d_in[10];
    const float* fg_b  = (const float*)d_in[11];
    const float* wg_W  = (const float*)d_in[12];
    const float* wg_b  = (const float*)d_in[13];
    const float* hsW1  = (const float*)d_in[14];
    const float* hsb1  = (const float*)d_in[15];
    const float* hsW2  = (const float*)d_in[16];
    const float* hsb2  = (const float*)d_in[17];
    const float* heW1  = (const float*)d_in[18];
    const float* heb1  = (const float*)d_in[19];
    const float* heW2  = (const float*)d_in[20];
    const float* heb2  = (const float*)d_in[21];
    const float* hfW1  = (const float*)d_in[22];
    const float* hfb1  = (const float*)d_in[23];
    const float* hfW2  = (const float*)d_in[24];
    const float* hfb2  = (const float*)d_in[25];
    const float* hwW1  = (const float*)d_in[26];
    const float* hwb1  = (const float*)d_in[27];
    const float* hwW2  = (const float*)d_in[28];
    const float* hwb2  = (const float*)d_in[29];

    __half *WP, *MEGA, *SCRATCH, *HEADH;
    cudaGetSymbolAddress((void**)&WP,      g_WP);
    cudaGetSymbolAddress((void**)&MEGA,    g_MEGA);
    cudaGetSymbolAddress((void**)&SCRATCH, g_SCRATCH);
    cudaGetSymbolAddress((void**)&HEADH,   g_HEADH);

    cudaFuncSetAttribute(gemm_lm<MODE_PLAIN>, cudaFuncAttributeMaxDynamicSharedMemorySize, GEMM_SMEM);
    cudaFuncSetAttribute(gemm_lm<MODE_ADD>,   cudaFuncAttributeMaxDynamicSharedMemorySize, GEMM_SMEM);
    cudaFuncSetAttribute(gemm_lm<MODE_GATE>,  cudaFuncAttributeMaxDynamicSharedMemorySize, GEMM_SMEM);
    cudaFuncSetAttribute(gemm_lm<MODE_GELU>,  cudaFuncAttributeMaxDynamicSharedMemorySize, GEMM_SMEM);

    split_inputs_kernel<<<(BATCH * HDIM + 255) / 256, 256>>>(sh, el, fa, wr);

    pack_tiled<<<dim3(16, 16, 5), 256>>>(s2e_W, WP + S2E_OFF, 512);
    pack_tiled<<<dim3(32, 16, 5), 256>>>(tf_W,  WP + TF_OFF,  1024);
    pack_tiled<<<dim3(16, 16, 5), 256>>>(fg_W,  WP + FG_OFF,  512);
    pack_tiled<<<dim3(32, 16, 5), 256>>>(fw_W,  WP + FW_OFF,  1024);
    pack_tiled<<<dim3(16, 16, 5), 256>>>(wg_W,  WP + WG_OFF,  512);
    pack_tiled<<<dim3(16, 16, 1), 256>>>(hsW1, WP + H1_OFF + 0 * S2E_SZ, 512);
    pack_tiled<<<dim3(16, 16, 1), 256>>>(heW1, WP + H1_OFF + 1 * S2E_SZ, 512);
    pack_tiled<<<dim3(16, 16, 1), 256>>>(hfW1, WP + H1_OFF + 2 * S2E_SZ, 512);
    pack_tiled<<<dim3(16, 16, 1), 256>>>(hwW1, WP + H1_OFF + 3 * S2E_SZ, 512);

    dim3 grid(BATCH / 128, 4, 1);
    auto B1 = [](const float* p) { Bias4 b; b.p[0] = b.p[1] = b.p[2] = b.p[3] = p; return b; };

    for (int i = 0; i < NL; i++) {
        // e = e + sh @ W + b
        gemm_lm<MODE_ADD><<<grid, 256, GEMM_SMEM>>>(
            MEGA, 4096, 0, 0, 512,
            WP + S2E_OFF + (size_t)i * S2E_SZ, 0, B1(s2e_b + i * 512),
            MEGA, 4096, 512, 2560, 0, nullptr, 0, 0);
        // fm = [sh_hi, e_hi] @ W + b -> SCRATCH (hi only)
        gemm_lm<MODE_PLAIN><<<grid, 256, GEMM_SMEM>>>(
            MEGA, 4096, 0, 0, 1024,
            WP + TF_OFF + (size_t)i * TF_SZ, 0, B1(tf_b + i * 512),
            SCRATCH, 512, 0, 0, 0, nullptr, 0, 0);
        // g = sigmoid(fm @ W + b); f = f*(1-g) + fm*g
        gemm_lm<MODE_GATE><<<grid, 256, GEMM_SMEM>>>(
            SCRATCH, 512, 0, 0, 512,
            WP + FG_OFF + (size_t)i * S2E_SZ, 0, B1(fg_b + i * 512),
            MEGA, 4096, 1024, 3072, 0, SCRATCH, 512, 0);
        // wm = [e_hi, f_hi] @ W + b
        gemm_lm<MODE_PLAIN><<<grid, 256, GEMM_SMEM>>>(
            MEGA, 4096, 512, 0, 1024,
            WP + FW_OFF + (size_t)i * TF_SZ, 0, B1(fw_b + i * 512),
            SCRATCH, 512, 0, 0, 0, nullptr, 0, 0);
        // g = sigmoid(wm @ W + b); w = w*(1-g) + wm*g
        gemm_lm<MODE_GATE><<<grid, 256, GEMM_SMEM>>>(
            SCRATCH, 512, 0, 0, 512,
            WP + WG_OFF + (size_t)i * S2E_SZ, 0, B1(wg_b + i * 512),
            MEGA, 4096, 1536, 3584, 0, SCRATCH, 512, 0);
    }

    // all 4 heads in one launch: z selects head
    {
        Bias4 hb; hb.p[0] = hsb1; hb.p[1] = heb1; hb.p[2] = hfb1; hb.p[3] = hwb1;
        dim3 grid4(BATCH / 128, 4, 4);
        gemm_lm<MODE_GELU><<<grid4, 256, GEMM_SMEM>>>(
            MEGA, 4096, 0, 512, 512,
            WP + H1_OFF, S2E_SZ, hb,
            HEADH, 512, 0, 0, BATCH * 512, nullptr, 0, 0);
    }

    head2_kernel<<<BATCH / 8, 256>>>(hsW2, hsb2, heW2, heb2, hfW2, hfb2,
                                     hwW2, hwb2, (float*)d_out);
}